// round 1
// baseline (speedup 1.0000x reference)
#include <cuda_runtime.h>
#include <stdint.h>

// Problem constants
#define BROWS   32768
#define C_IN    768
#define H1      512
#define H2      256
#define H3      256
#define DECH    256
#define LATENT  128
#define KCAT    8
#define MAXT    (BROWS/128 + KCAT)   // 264 max decoder tiles

// ---------------- scratch (static device globals; no allocation) ------------
__device__ float g_h1[BROWS * H1];
__device__ float g_h2[BROWS * H2];
__device__ float g_h3[BROWS * H3];
__device__ float g_d1[BROWS * DECH];
__device__ float g_d2[BROWS * DECH];

__device__ int g_perm[BROWS];
__device__ int g_counts[KCAT];
__device__ int g_cursor[KCAT];
__device__ int g_offsets[KCAT + 1];
__device__ int g_tile_cat[MAXT];
__device__ int g_tile_row0[MAXT];
__device__ int g_tile_rows[MAXT];
__device__ int g_ntiles;
__device__ int g_is32;   // 1 if cat_idx buffer is int32, 0 if int64

// ---------------- routing kernels -------------------------------------------
__global__ void k_zero() {
    if (threadIdx.x < KCAT) { g_counts[threadIdx.x] = 0; g_cursor[threadIdx.x] = 0; }
    if (threadIdx.x == 0)   { g_is32 = 0; g_ntiles = 0; }
}

// Detect cat_idx dtype: interpret first BROWS/2 int64 slots (always in-bounds
// for both dtypes). If the buffer is really int64, every value is in [0,8).
// If it's int32, pairs combine to huge values with overwhelming probability.
__global__ void k_detect(const void* cat) {
    const long long* p = (const long long*)cat;
    int i = blockIdx.x * blockDim.x + threadIdx.x;
    int bad = 0;
    for (; i < BROWS / 2; i += gridDim.x * blockDim.x) {
        long long v = p[i];
        if (v < 0 || v >= KCAT) bad = 1;
    }
    if (bad) atomicOr(&g_is32, 1);
}

__device__ __forceinline__ int cat_at(const void* cat, int i) {
    int v = g_is32 ? (int)((const int*)cat)[i] : (int)((const long long*)cat)[i];
    return (v < 0) ? 0 : (v >= KCAT ? KCAT - 1 : v);
}

__global__ void k_hist(const void* cat) {
    int i = blockIdx.x * blockDim.x + threadIdx.x;
    for (; i < BROWS; i += gridDim.x * blockDim.x)
        atomicAdd(&g_counts[cat_at(cat, i)], 1);
}

__global__ void k_scan() {
    if (threadIdx.x != 0 || blockIdx.x != 0) return;
    int off = 0, t = 0;
    for (int k = 0; k < KCAT; k++) {
        g_offsets[k] = off;
        int cnt = g_counts[k];
        for (int r = 0; r < cnt; r += 128) {
            g_tile_cat[t]  = k;
            g_tile_row0[t] = off + r;
            g_tile_rows[t] = (cnt - r < 128) ? (cnt - r) : 128;
            t++;
        }
        off += cnt;
    }
    g_offsets[KCAT] = off;
    g_ntiles = t;
}

__global__ void k_perm(const void* cat) {
    int i = blockIdx.x * blockDim.x + threadIdx.x;
    for (; i < BROWS; i += gridDim.x * blockDim.x) {
        int k = cat_at(cat, i);
        int pos = atomicAdd(&g_cursor[k], 1);
        g_perm[g_offsets[k] + pos] = i;
    }
}

// ---------------- dense GEMM: C = act(A @ B + bias) --------------------------
// A: [M, Kdim] row-major, B: [Kdim, N] row-major, C: [M, N].
// Block tile 128x128, K-tile 16, 256 threads, 8x8 per-thread tile.
// M = 32768 (multiple of 128); N, Kdim multiples of 128/16 — no guards needed.
template<bool RELU>
__global__ __launch_bounds__(256)
void k_gemm(const float* __restrict__ A, const float* __restrict__ Bw,
            const float* __restrict__ bias, float* __restrict__ Cw,
            int N, int Kdim)
{
    __shared__ float As[2][16][128];
    __shared__ float Bs[2][16][128];

    const int tid = threadIdx.x;
    const int m0 = blockIdx.y * 128;
    const int n0 = blockIdx.x * 128;
    const int tx = tid & 15;
    const int ty = tid >> 4;
    const int av = tid * 2;   // this thread's two float4 slots

    float acc[8][8];
#pragma unroll
    for (int i = 0; i < 8; i++)
#pragma unroll
        for (int j = 0; j < 8; j++) acc[i][j] = 0.f;

    const int Kt = Kdim >> 4;

    // prologue: stage 0
#pragma unroll
    for (int s = 0; s < 2; s++) {
        int v = av + s;
        int arow = v >> 2, ac = (v & 3) * 4;
        float4 a = *(const float4*)&A[(size_t)(m0 + arow) * Kdim + ac];
        As[0][ac + 0][arow] = a.x; As[0][ac + 1][arow] = a.y;
        As[0][ac + 2][arow] = a.z; As[0][ac + 3][arow] = a.w;
        int brow = v >> 5, bcol = (v & 31) * 4;
        *(float4*)&Bs[0][brow][bcol] = *(const float4*)&Bw[(size_t)brow * N + n0 + bcol];
    }
    __syncthreads();

    for (int kt = 0; kt < Kt; kt++) {
        const int cur = kt & 1, nxt = cur ^ 1;
        const bool pref = (kt + 1) < Kt;
        float4 pa[2], pb[2];
        if (pref) {
            const int k0 = (kt + 1) << 4;
#pragma unroll
            for (int s = 0; s < 2; s++) {
                int v = av + s;
                int arow = v >> 2, ac = (v & 3) * 4;
                pa[s] = *(const float4*)&A[(size_t)(m0 + arow) * Kdim + k0 + ac];
                int brow = v >> 5, bcol = (v & 31) * 4;
                pb[s] = *(const float4*)&Bw[(size_t)(k0 + brow) * N + n0 + bcol];
            }
        }
#pragma unroll
        for (int k = 0; k < 16; k++) {
            float ra[8], rb[8];
            *(float4*)&ra[0] = *(const float4*)&As[cur][k][ty * 8];
            *(float4*)&ra[4] = *(const float4*)&As[cur][k][ty * 8 + 4];
            *(float4*)&rb[0] = *(const float4*)&Bs[cur][k][tx * 4];
            *(float4*)&rb[4] = *(const float4*)&Bs[cur][k][64 + tx * 4];
#pragma unroll
            for (int i = 0; i < 8; i++)
#pragma unroll
                for (int j = 0; j < 8; j++)
                    acc[i][j] += ra[i] * rb[j];
        }
        if (pref) {
#pragma unroll
            for (int s = 0; s < 2; s++) {
                int v = av + s;
                int arow = v >> 2, ac = (v & 3) * 4;
                As[nxt][ac + 0][arow] = pa[s].x; As[nxt][ac + 1][arow] = pa[s].y;
                As[nxt][ac + 2][arow] = pa[s].z; As[nxt][ac + 3][arow] = pa[s].w;
                int brow = v >> 5, bcol = (v & 31) * 4;
                *(float4*)&Bs[nxt][brow][bcol] = pb[s];
            }
            __syncthreads();
        }
    }

    // epilogue
    float bv[8];
    *(float4*)&bv[0] = *(const float4*)&bias[n0 + tx * 4];
    *(float4*)&bv[4] = *(const float4*)&bias[n0 + 64 + tx * 4];
#pragma unroll
    for (int i = 0; i < 8; i++) {
        const int m = m0 + ty * 8 + i;
        float4 o0, o1;
        o0.x = acc[i][0] + bv[0]; o0.y = acc[i][1] + bv[1];
        o0.z = acc[i][2] + bv[2]; o0.w = acc[i][3] + bv[3];
        o1.x = acc[i][4] + bv[4]; o1.y = acc[i][5] + bv[5];
        o1.z = acc[i][6] + bv[6]; o1.w = acc[i][7] + bv[7];
        if (RELU) {
            o0.x = fmaxf(o0.x, 0.f); o0.y = fmaxf(o0.y, 0.f);
            o0.z = fmaxf(o0.z, 0.f); o0.w = fmaxf(o0.w, 0.f);
            o1.x = fmaxf(o1.x, 0.f); o1.y = fmaxf(o1.y, 0.f);
            o1.z = fmaxf(o1.z, 0.f); o1.w = fmaxf(o1.w, 0.f);
        }
        *(float4*)&Cw[(size_t)m * N + n0 + tx * 4]      = o0;
        *(float4*)&Cw[(size_t)m * N + n0 + 64 + tx * 4] = o1;
    }
}

// ---------------- grouped (routed) decoder GEMM ------------------------------
// Tile t picks category + sorted-row range from the device tile table.
// GATHER: A row index = g_perm[sorted_row] (used by decoder layer 1).
// SCATTER: output row index = g_perm[sorted_row] (used by decoder layer 3).
template<bool GATHER, bool SCATTER, bool RELU>
__global__ __launch_bounds__(256)
void k_gemm_dec(const float* __restrict__ A, const float* __restrict__ Wbase,
                const float* __restrict__ biasbase, float* __restrict__ Cw,
                int N, int Kdim, int wstride, int bstride)
{
    const int t = blockIdx.y;
    if (t >= g_ntiles) return;
    const int cat   = g_tile_cat[t];
    const int row0  = g_tile_row0[t];
    const int nrows = g_tile_rows[t];

    const float* __restrict__ Bw   = Wbase + (size_t)cat * wstride;
    const float* __restrict__ bias = biasbase + (size_t)cat * bstride;

    __shared__ float As[2][16][128];
    __shared__ float Bs[2][16][128];

    const int tid = threadIdx.x;
    const int n0 = blockIdx.x * 128;
    const int tx = tid & 15;
    const int ty = tid >> 4;
    const int av = tid * 2;

    // Precompute this thread's two A-source rows (valid pointers even for
    // padded rows — garbage values are finite and never stored).
    int arowA[2], arowIdx[2], acA[2];
#pragma unroll
    for (int s = 0; s < 2; s++) {
        int v = av + s;
        int r = v >> 2;
        acA[s] = (v & 3) * 4;
        arowA[s] = r;
        int sr = (r < nrows) ? (row0 + r) : row0;     // clamp to a valid sorted row
        arowIdx[s] = GATHER ? g_perm[sr] : sr;
    }

    float acc[8][8];
#pragma unroll
    for (int i = 0; i < 8; i++)
#pragma unroll
        for (int j = 0; j < 8; j++) acc[i][j] = 0.f;

    const int Kt = Kdim >> 4;

#pragma unroll
    for (int s = 0; s < 2; s++) {
        int v = av + s;
        float4 a = *(const float4*)&A[(size_t)arowIdx[s] * Kdim + acA[s]];
        As[0][acA[s] + 0][arowA[s]] = a.x; As[0][acA[s] + 1][arowA[s]] = a.y;
        As[0][acA[s] + 2][arowA[s]] = a.z; As[0][acA[s] + 3][arowA[s]] = a.w;
        int brow = v >> 5, bcol = (v & 31) * 4;
        *(float4*)&Bs[0][brow][bcol] = *(const float4*)&Bw[(size_t)brow * N + n0 + bcol];
    }
    __syncthreads();

    for (int kt = 0; kt < Kt; kt++) {
        const int cur = kt & 1, nxt = cur ^ 1;
        const bool pref = (kt + 1) < Kt;
        float4 pa[2], pb[2];
        if (pref) {
            const int k0 = (kt + 1) << 4;
#pragma unroll
            for (int s = 0; s < 2; s++) {
                int v = av + s;
                pa[s] = *(const float4*)&A[(size_t)arowIdx[s] * Kdim + k0 + acA[s]];
                int brow = v >> 5, bcol = (v & 31) * 4;
                pb[s] = *(const float4*)&Bw[(size_t)(k0 + brow) * N + n0 + bcol];
            }
        }
#pragma unroll
        for (int k = 0; k < 16; k++) {
            float ra[8], rb[8];
            *(float4*)&ra[0] = *(const float4*)&As[cur][k][ty * 8];
            *(float4*)&ra[4] = *(const float4*)&As[cur][k][ty * 8 + 4];
            *(float4*)&rb[0] = *(const float4*)&Bs[cur][k][tx * 4];
            *(float4*)&rb[4] = *(const float4*)&Bs[cur][k][64 + tx * 4];
#pragma unroll
            for (int i = 0; i < 8; i++)
#pragma unroll
                for (int j = 0; j < 8; j++)
                    acc[i][j] += ra[i] * rb[j];
        }
        if (pref) {
#pragma unroll
            for (int s = 0; s < 2; s++) {
                int v = av + s;
                As[nxt][acA[s] + 0][arowA[s]] = pa[s].x; As[nxt][acA[s] + 1][arowA[s]] = pa[s].y;
                As[nxt][acA[s] + 2][arowA[s]] = pa[s].z; As[nxt][acA[s] + 3][arowA[s]] = pa[s].w;
                int brow = v >> 5, bcol = (v & 31) * 4;
                *(float4*)&Bs[nxt][brow][bcol] = pb[s];
            }
            __syncthreads();
        }
    }

    float bv[8];
    *(float4*)&bv[0] = *(const float4*)&bias[n0 + tx * 4];
    *(float4*)&bv[4] = *(const float4*)&bias[n0 + 64 + tx * 4];
#pragma unroll
    for (int i = 0; i < 8; i++) {
        const int r = ty * 8 + i;
        if (r >= nrows) continue;
        const int sr = row0 + r;
        const int orow = SCATTER ? g_perm[sr] : sr;
        float4 o0, o1;
        o0.x = acc[i][0] + bv[0]; o0.y = acc[i][1] + bv[1];
        o0.z = acc[i][2] + bv[2]; o0.w = acc[i][3] + bv[3];
        o1.x = acc[i][4] + bv[4]; o1.y = acc[i][5] + bv[5];
        o1.z = acc[i][6] + bv[6]; o1.w = acc[i][7] + bv[7];
        if (RELU) {
            o0.x = fmaxf(o0.x, 0.f); o0.y = fmaxf(o0.y, 0.f);
            o0.z = fmaxf(o0.z, 0.f); o0.w = fmaxf(o0.w, 0.f);
            o1.x = fmaxf(o1.x, 0.f); o1.y = fmaxf(o1.y, 0.f);
            o1.z = fmaxf(o1.z, 0.f); o1.w = fmaxf(o1.w, 0.f);
        }
        *(float4*)&Cw[(size_t)orow * N + n0 + tx * 4]      = o0;
        *(float4*)&Cw[(size_t)orow * N + n0 + 64 + tx * 4] = o1;
    }
}

// ---------------- launch -----------------------------------------------------
extern "C" void kernel_launch(void* const* d_in, const int* in_sizes, int n_in,
                              void* d_out, int out_size)
{
    const float* feat = (const float*)d_in[0];
    const float* We1  = (const float*)d_in[1];
    const float* be1  = (const float*)d_in[2];
    const float* We2  = (const float*)d_in[3];
    const float* be2  = (const float*)d_in[4];
    const float* We3  = (const float*)d_in[5];
    const float* be3  = (const float*)d_in[6];
    const float* Wd1  = (const float*)d_in[7];
    const float* bd1  = (const float*)d_in[8];
    const float* Wd2  = (const float*)d_in[9];
    const float* bd2  = (const float*)d_in[10];
    const float* Wd3  = (const float*)d_in[11];
    const float* bd3  = (const float*)d_in[12];
    const void*  cat  = (const void*)d_in[13];
    float* out = (float*)d_out;

    float *p_h1, *p_h2, *p_h3, *p_d1, *p_d2;
    cudaGetSymbolAddress((void**)&p_h1, g_h1);
    cudaGetSymbolAddress((void**)&p_h2, g_h2);
    cudaGetSymbolAddress((void**)&p_h3, g_h3);
    cudaGetSymbolAddress((void**)&p_d1, g_d1);
    cudaGetSymbolAddress((void**)&p_d2, g_d2);

    // routing
    k_zero<<<1, 32>>>();
    k_detect<<<64, 256>>>(cat);
    k_hist<<<64, 256>>>(cat);
    k_scan<<<1, 1>>>();
    k_perm<<<64, 256>>>(cat);

    // shared encoder
    k_gemm<true ><<<dim3(H1 / 128, BROWS / 128), 256>>>(feat, We1, be1, p_h1, H1, C_IN);
    k_gemm<true ><<<dim3(H2 / 128, BROWS / 128), 256>>>(p_h1, We2, be2, p_h2, H2, H1);
    k_gemm<false><<<dim3(H3 / 128, BROWS / 128), 256>>>(p_h2, We3, be3, p_h3, H3, H2);

    // routed per-category decoders
    k_gemm_dec<true,  false, true ><<<dim3(DECH / 128, MAXT), 256>>>(
        p_h3, Wd1, bd1, p_d1, DECH, H3, H3 * DECH, DECH);
    k_gemm_dec<false, false, true ><<<dim3(DECH / 128, MAXT), 256>>>(
        p_d1, Wd2, bd2, p_d2, DECH, DECH, DECH * DECH, DECH);
    k_gemm_dec<false, true,  false><<<dim3(LATENT / 128, MAXT), 256>>>(
        p_d2, Wd3, bd3, out, LATENT, DECH, DECH * LATENT, LATENT);
}

// round 10
// speedup vs baseline: 1.6033x; 1.6033x over previous
#include <cuda_runtime.h>
#include <cuda_bf16.h>
#include <stdint.h>

// ---------------- problem constants -----------------------------------------
#define BROWS   32768
#define C_IN    768
#define H1      512
#define H2      256
#define H3      256
#define DECH    256
#define LATENT  128
#define KCAT    8
#define MAXT    (BROWS/128 + KCAT)   // 264 max decoder tiles

// ---------------- scratch (static device globals) ---------------------------
// features + activations as bf16 hi/lo pairs
__device__ __nv_bfloat16 g_xh[BROWS * C_IN],  g_xl[BROWS * C_IN];
__device__ __nv_bfloat16 g_h1h[BROWS * H1],   g_h1l[BROWS * H1];
__device__ __nv_bfloat16 g_h2h[BROWS * H2],   g_h2l[BROWS * H2];
__device__ __nv_bfloat16 g_h3h[BROWS * H3],   g_h3l[BROWS * H3];
__device__ __nv_bfloat16 g_d1h[BROWS * DECH], g_d1l[BROWS * DECH];
__device__ __nv_bfloat16 g_d2h[BROWS * DECH], g_d2l[BROWS * DECH];

// transposed weights [N, K] as bf16 hi/lo
__device__ __nv_bfloat16 g_we1h[H1 * C_IN],          g_we1l[H1 * C_IN];
__device__ __nv_bfloat16 g_we2h[H2 * H1],            g_we2l[H2 * H1];
__device__ __nv_bfloat16 g_we3h[H3 * H2],            g_we3l[H3 * H2];
__device__ __nv_bfloat16 g_wd1h[KCAT * DECH * H3],   g_wd1l[KCAT * DECH * H3];
__device__ __nv_bfloat16 g_wd2h[KCAT * DECH * DECH], g_wd2l[KCAT * DECH * DECH];
__device__ __nv_bfloat16 g_wd3h[KCAT * LATENT * DECH], g_wd3l[KCAT * LATENT * DECH];

// routing state
__device__ int g_perm[BROWS];
__device__ int g_counts[KCAT];
__device__ int g_cursor[KCAT];
__device__ int g_offsets[KCAT + 1];
__device__ int g_tile_cat[MAXT];
__device__ int g_tile_row0[MAXT];
__device__ int g_tile_rows[MAXT];
__device__ int g_ntiles;
__device__ int g_is32;

// ---------------- PTX helpers (baseline PTX only — no 'a' features) ---------
__device__ __forceinline__ uint32_t s2u(const void* p) {
    uint32_t a;
    asm("{ .reg .u64 t; cvta.to.shared.u64 t, %1; cvt.u32.u64 %0, t; }" : "=r"(a) : "l"(p));
    return a;
}

__device__ __forceinline__ void ldsm4(uint32_t* r, uint32_t addr) {
    asm volatile("ldmatrix.sync.aligned.m8n8.x4.shared.b16 {%0,%1,%2,%3}, [%4];"
                 : "=r"(r[0]), "=r"(r[1]), "=r"(r[2]), "=r"(r[3]) : "r"(addr));
}

__device__ __forceinline__ void mma16816(float* c, const uint32_t* a, const uint32_t* b) {
    asm volatile(
        "mma.sync.aligned.m16n8k16.row.col.f32.bf16.bf16.f32 "
        "{%0,%1,%2,%3}, {%4,%5,%6,%7}, {%8,%9}, {%0,%1,%2,%3};"
        : "+f"(c[0]), "+f"(c[1]), "+f"(c[2]), "+f"(c[3])
        : "r"(a[0]), "r"(a[1]), "r"(a[2]), "r"(a[3]), "r"(b[0]), "r"(b[1]));
}

#define CPA16(s, g)  asm volatile("cp.async.cg.shared.global [%0], [%1], 16;" :: "r"(s), "l"(g))
#define CPCOMMIT()   asm volatile("cp.async.commit_group;" ::: "memory")
#define CPWAIT(n)    asm volatile("cp.async.wait_group %0;" :: "n"(n) : "memory")

// ---------------- routing kernels --------------------------------------------
__global__ void k_zero() {
    if (threadIdx.x < KCAT) { g_counts[threadIdx.x] = 0; g_cursor[threadIdx.x] = 0; }
    if (threadIdx.x == 0)   { g_is32 = 0; g_ntiles = 0; }
}
__global__ void k_detect(const void* cat) {
    const long long* p = (const long long*)cat;
    int i = blockIdx.x * blockDim.x + threadIdx.x;
    int bad = 0;
    for (; i < BROWS / 2; i += gridDim.x * blockDim.x) {
        long long v = p[i];
        if (v < 0 || v >= KCAT) bad = 1;
    }
    if (bad) atomicOr(&g_is32, 1);
}
__device__ __forceinline__ int cat_at(const void* cat, int i) {
    int v = g_is32 ? (int)((const int*)cat)[i] : (int)((const long long*)cat)[i];
    return (v < 0) ? 0 : (v >= KCAT ? KCAT - 1 : v);
}
__global__ void k_hist(const void* cat) {
    int i = blockIdx.x * blockDim.x + threadIdx.x;
    for (; i < BROWS; i += gridDim.x * blockDim.x)
        atomicAdd(&g_counts[cat_at(cat, i)], 1);
}
__global__ void k_scan() {
    if (threadIdx.x != 0 || blockIdx.x != 0) return;
    int off = 0, t = 0;
    for (int k = 0; k < KCAT; k++) {
        g_offsets[k] = off;
        int cnt = g_counts[k];
        for (int r = 0; r < cnt; r += 128) {
            g_tile_cat[t]  = k;
            g_tile_row0[t] = off + r;
            g_tile_rows[t] = (cnt - r < 128) ? (cnt - r) : 128;
            t++;
        }
        off += cnt;
    }
    g_offsets[KCAT] = off;
    g_ntiles = t;
}
__global__ void k_perm(const void* cat) {
    int i = blockIdx.x * blockDim.x + threadIdx.x;
    for (; i < BROWS; i += gridDim.x * blockDim.x) {
        int k = cat_at(cat, i);
        int pos = atomicAdd(&g_cursor[k], 1);
        g_perm[g_offsets[k] + pos] = i;
    }
}

// ---------------- prep kernels -----------------------------------------------
// weights: src [ncat, Kd, N] fp32 -> [ncat, N, Kd] bf16 hi/lo
__global__ void k_wprep(const float* __restrict__ src,
                        __nv_bfloat16* __restrict__ dh, __nv_bfloat16* __restrict__ dl,
                        int Kd, int N, int total)
{
    int idx = blockIdx.x * blockDim.x + threadIdx.x;
    for (; idx < total; idx += gridDim.x * blockDim.x) {
        int c = idx / (Kd * N);
        int rem = idx - c * Kd * N;
        int r = rem / N;
        int n = rem - r * N;
        float v = src[idx];
        __nv_bfloat16 h = __float2bfloat16(v);
        __nv_bfloat16 l = __float2bfloat16(v - __bfloat162float(h));
        int o = c * Kd * N + n * Kd + r;
        dh[o] = h; dl[o] = l;
    }
}
// features: fp32 -> bf16 hi/lo (same layout)
__global__ void k_xprep(const float* __restrict__ src,
                        __nv_bfloat16* __restrict__ dh, __nv_bfloat16* __restrict__ dl,
                        int total4)
{
    int idx = blockIdx.x * blockDim.x + threadIdx.x;
    for (; idx < total4; idx += gridDim.x * blockDim.x) {
        float4 v = ((const float4*)src)[idx];
        union { __nv_bfloat16 b[4]; uint2 u; } hh, ll;
        hh.b[0] = __float2bfloat16(v.x); ll.b[0] = __float2bfloat16(v.x - __bfloat162float(hh.b[0]));
        hh.b[1] = __float2bfloat16(v.y); ll.b[1] = __float2bfloat16(v.y - __bfloat162float(hh.b[1]));
        hh.b[2] = __float2bfloat16(v.z); ll.b[2] = __float2bfloat16(v.z - __bfloat162float(hh.b[2]));
        hh.b[3] = __float2bfloat16(v.w); ll.b[3] = __float2bfloat16(v.w - __bfloat162float(hh.b[3]));
        ((uint2*)dh)[idx] = hh.u;
        ((uint2*)dl)[idx] = ll.u;
    }
}

// ---------------- HMMA GEMM ---------------------------------------------------
// C[128x128 tile] = act( A[128,K] @ W[N,K]^T + bias )  via split-bf16 3-pass:
//   D += Ahi*Bhi^T + Ahi*Blo^T + Alo*Bhi^T   (fp32 accumulators)
// mma.sync.m16n8k16 (baseline PTX -> HMMA), ldmatrix frags, cp.async staging.
// SMEM per stage: 4 arrays (Ah,Al,Bh,Bl), each 128 rows x 40 bf16 (80B, padded).
#define ROWB    80          // padded row bytes (32 data bf16 + 8 pad)
#define ARR_B   (128*ROWB)  // 10240
#define STG_B   (4*ARR_B)   // 40960
#define SMEM_DYN (2*STG_B + 512)

template<bool DEC, bool GATHER, bool SCATTER, bool RELU, bool OUTF32>
__global__ void __launch_bounds__(256, 1)
k_mgemm(const __nv_bfloat16* __restrict__ Ahi, const __nv_bfloat16* __restrict__ Alo,
        const __nv_bfloat16* __restrict__ Whi, const __nv_bfloat16* __restrict__ Wlo,
        const float* __restrict__ biasb,
        float* __restrict__ Of, __nv_bfloat16* __restrict__ Ohi, __nv_bfloat16* __restrict__ Olo,
        int Kdim, int Nout, int wstride, int bstride)
{
    int cat = 0, row0, nrows;
    if (DEC) {
        int t = blockIdx.y;
        if (t >= g_ntiles) return;
        cat = g_tile_cat[t]; row0 = g_tile_row0[t]; nrows = g_tile_rows[t];
    } else {
        row0 = blockIdx.y * 128; nrows = 128;
    }
    const int n0 = blockIdx.x * 128;
    const int tid = threadIdx.x;
    const int wid = tid >> 5, lane = tid & 31;

    extern __shared__ char smraw[];
    const uint32_t sb = s2u(smraw);
    float* const bias_s = (float*)(smraw + 2 * STG_B);

    if (tid < 128) bias_s[tid] = biasb[(size_t)cat * bstride + n0 + tid];

    // ---- staging map: thread t -> row = t>>1, K-half = t&1 (16 bf16 = 32B)
    const int srow = tid >> 1, shalf = tid & 1;
    const int rr = (srow < nrows) ? srow : 0;
    const int arow = GATHER ? g_perm[row0 + rr] : (row0 + rr);
    const __nv_bfloat16* gAh = Ahi + (size_t)arow * Kdim + shalf * 16;
    const __nv_bfloat16* gAl = Alo + (size_t)arow * Kdim + shalf * 16;
    const __nv_bfloat16* gBh = Whi + (size_t)cat * wstride + (size_t)(n0 + srow) * Kdim + shalf * 16;
    const __nv_bfloat16* gBl = Wlo + (size_t)cat * wstride + (size_t)(n0 + srow) * Kdim + shalf * 16;
    const uint32_t so = (uint32_t)srow * ROWB + (uint32_t)shalf * 32;

    // ---- fragment ldmatrix lane addressing (byte offsets, invariant parts)
    const int wm = wid & 1;          // 2 warps along M (64 rows each)
    const int wn = wid >> 1;         // 4 warps along N (32 cols each)
    const uint32_t aRow = (uint32_t)(wm * 64 + (lane & 15));
    const uint32_t aK   = (uint32_t)((lane >> 4) << 3);
    const uint32_t bRow = (uint32_t)(wn * 32 + ((lane >> 4) << 3) + (lane & 7));
    const uint32_t bK   = (uint32_t)(((lane >> 3) & 1) << 3);

    float acc[4][4][4];
#pragma unroll
    for (int i = 0; i < 4; i++)
#pragma unroll
        for (int j = 0; j < 4; j++)
#pragma unroll
            for (int c = 0; c < 4; c++) acc[i][j][c] = 0.f;

    const int nch = Kdim >> 5;   // chunks of 32

    // ---- prologue: stage chunk 0 into buffer 0
    {
        const uint32_t d = sb + so;
        CPA16(d + 0*ARR_B +  0, (const char*)(gAh) + 0);
        CPA16(d + 0*ARR_B + 16, (const char*)(gAh) + 16);
        CPA16(d + 1*ARR_B +  0, (const char*)(gAl) + 0);
        CPA16(d + 1*ARR_B + 16, (const char*)(gAl) + 16);
        CPA16(d + 2*ARR_B +  0, (const char*)(gBh) + 0);
        CPA16(d + 2*ARR_B + 16, (const char*)(gBh) + 16);
        CPA16(d + 3*ARR_B +  0, (const char*)(gBl) + 0);
        CPA16(d + 3*ARR_B + 16, (const char*)(gBl) + 16);
        CPCOMMIT();
    }

    for (int s = 0; s < nch; s++) {
        // issue chunk s+1 into the other buffer
        if (s + 1 < nch) {
            const uint32_t d = sb + ((s + 1) & 1) * STG_B + so;
            const size_t go = (size_t)(s + 1) * 32 * sizeof(__nv_bfloat16);
            CPA16(d + 0*ARR_B +  0, (const char*)(gAh) + go + 0);
            CPA16(d + 0*ARR_B + 16, (const char*)(gAh) + go + 16);
            CPA16(d + 1*ARR_B +  0, (const char*)(gAl) + go + 0);
            CPA16(d + 1*ARR_B + 16, (const char*)(gAl) + go + 16);
            CPA16(d + 2*ARR_B +  0, (const char*)(gBh) + go + 0);
            CPA16(d + 2*ARR_B + 16, (const char*)(gBh) + go + 16);
            CPA16(d + 3*ARR_B +  0, (const char*)(gBl) + go + 0);
            CPA16(d + 3*ARR_B + 16, (const char*)(gBl) + go + 16);
            CPCOMMIT();
            CPWAIT(1);
        } else {
            CPWAIT(0);
        }
        __syncthreads();

        const uint32_t st = sb + (s & 1) * STG_B;
        const uint32_t Ah_b = st, Al_b = st + ARR_B, Bh_b = st + 2*ARR_B, Bl_b = st + 3*ARR_B;

#pragma unroll
        for (int k0 = 0; k0 < 32; k0 += 16) {
            uint32_t ah[4][4], al[4][4], bh[2][4], bl[2][4];
            const uint32_t akk = (uint32_t)(k0) * 2 + aK * 2;
            const uint32_t bkk = (uint32_t)(k0) * 2 + bK * 2;
#pragma unroll
            for (int bm = 0; bm < 4; bm++) {
                const uint32_t ro = (aRow + bm * 16) * ROWB + akk;
                ldsm4(ah[bm], Ah_b + ro);
                ldsm4(al[bm], Al_b + ro);
            }
#pragma unroll
            for (int bp = 0; bp < 2; bp++) {
                const uint32_t ro = (bRow + bp * 16) * ROWB + bkk;
                ldsm4(bh[bp], Bh_b + ro);
                ldsm4(bl[bp], Bl_b + ro);
            }
#pragma unroll
            for (int bm = 0; bm < 4; bm++)
#pragma unroll
                for (int bn = 0; bn < 4; bn++) {
                    const uint32_t* fh = &bh[bn >> 1][(bn & 1) * 2];
                    const uint32_t* fl = &bl[bn >> 1][(bn & 1) * 2];
                    mma16816(acc[bm][bn], ah[bm], fh);
                    mma16816(acc[bm][bn], ah[bm], fl);
                    mma16816(acc[bm][bn], al[bm], fh);
                }
        }
        __syncthreads();
    }

    // ---- epilogue: D-frag mapping: c0,c1 -> row lane>>2, cols (lane&3)*2+{0,1};
    //                c2,c3 -> row +8.
    const int ecol = (lane & 3) * 2;
    const int erow = lane >> 2;
#pragma unroll
    for (int bm = 0; bm < 4; bm++) {
#pragma unroll
        for (int half = 0; half < 2; half++) {
            const int er = wm * 64 + bm * 16 + erow + half * 8;
            if (er >= nrows) continue;
            const int orow = SCATTER ? g_perm[row0 + er] : (row0 + er);
#pragma unroll
            for (int bn = 0; bn < 4; bn++) {
                const int cl = wn * 32 + bn * 8 + ecol;
                float v0 = acc[bm][bn][half * 2 + 0] + bias_s[cl + 0];
                float v1 = acc[bm][bn][half * 2 + 1] + bias_s[cl + 1];
                if (RELU) { v0 = fmaxf(v0, 0.f); v1 = fmaxf(v1, 0.f); }
                if (OUTF32) {
                    float2 o; o.x = v0; o.y = v1;
                    *(float2*)&Of[(size_t)orow * Nout + n0 + cl] = o;
                } else {
                    union { __nv_bfloat16 b[2]; uint32_t u; } hh, ll;
                    hh.b[0] = __float2bfloat16(v0);
                    hh.b[1] = __float2bfloat16(v1);
                    ll.b[0] = __float2bfloat16(v0 - __bfloat162float(hh.b[0]));
                    ll.b[1] = __float2bfloat16(v1 - __bfloat162float(hh.b[1]));
                    *(uint32_t*)&Ohi[(size_t)orow * Nout + n0 + cl] = hh.u;
                    *(uint32_t*)&Olo[(size_t)orow * Nout + n0 + cl] = ll.u;
                }
            }
        }
    }
}

// ---------------- launch -----------------------------------------------------
extern "C" void kernel_launch(void* const* d_in, const int* in_sizes, int n_in,
                              void* d_out, int out_size)
{
    const float* feat = (const float*)d_in[0];
    const float* We1  = (const float*)d_in[1];
    const float* be1  = (const float*)d_in[2];
    const float* We2  = (const float*)d_in[3];
    const float* be2  = (const float*)d_in[4];
    const float* We3  = (const float*)d_in[5];
    const float* be3  = (const float*)d_in[6];
    const float* Wd1  = (const float*)d_in[7];
    const float* bd1  = (const float*)d_in[8];
    const float* Wd2  = (const float*)d_in[9];
    const float* bd2  = (const float*)d_in[10];
    const float* Wd3  = (const float*)d_in[11];
    const float* bd3  = (const float*)d_in[12];
    const void*  cat  = (const void*)d_in[13];
    float* out = (float*)d_out;

    void *xh, *xl, *h1h, *h1l, *h2h, *h2l, *h3h, *h3l, *d1h, *d1l, *d2h, *d2l;
    void *we1h, *we1l, *we2h, *we2l, *we3h, *we3l;
    void *wd1h, *wd1l, *wd2h, *wd2l, *wd3h, *wd3l;
    cudaGetSymbolAddress(&xh, g_xh);   cudaGetSymbolAddress(&xl, g_xl);
    cudaGetSymbolAddress(&h1h, g_h1h); cudaGetSymbolAddress(&h1l, g_h1l);
    cudaGetSymbolAddress(&h2h, g_h2h); cudaGetSymbolAddress(&h2l, g_h2l);
    cudaGetSymbolAddress(&h3h, g_h3h); cudaGetSymbolAddress(&h3l, g_h3l);
    cudaGetSymbolAddress(&d1h, g_d1h); cudaGetSymbolAddress(&d1l, g_d1l);
    cudaGetSymbolAddress(&d2h, g_d2h); cudaGetSymbolAddress(&d2l, g_d2l);
    cudaGetSymbolAddress(&we1h, g_we1h); cudaGetSymbolAddress(&we1l, g_we1l);
    cudaGetSymbolAddress(&we2h, g_we2h); cudaGetSymbolAddress(&we2l, g_we2l);
    cudaGetSymbolAddress(&we3h, g_we3h); cudaGetSymbolAddress(&we3l, g_we3l);
    cudaGetSymbolAddress(&wd1h, g_wd1h); cudaGetSymbolAddress(&wd1l, g_wd1l);
    cudaGetSymbolAddress(&wd2h, g_wd2h); cudaGetSymbolAddress(&wd2l, g_wd2l);
    cudaGetSymbolAddress(&wd3h, g_wd3h); cudaGetSymbolAddress(&wd3l, g_wd3l);

    cudaFuncSetAttribute(k_mgemm<false, false, false, true,  false>,
                         cudaFuncAttributeMaxDynamicSharedMemorySize, SMEM_DYN);
    cudaFuncSetAttribute(k_mgemm<false, false, false, false, false>,
                         cudaFuncAttributeMaxDynamicSharedMemorySize, SMEM_DYN);
    cudaFuncSetAttribute(k_mgemm<true,  true,  false, true,  false>,
                         cudaFuncAttributeMaxDynamicSharedMemorySize, SMEM_DYN);
    cudaFuncSetAttribute(k_mgemm<true,  false, false, true,  false>,
                         cudaFuncAttributeMaxDynamicSharedMemorySize, SMEM_DYN);
    cudaFuncSetAttribute(k_mgemm<true,  false, true,  false, true >,
                         cudaFuncAttributeMaxDynamicSharedMemorySize, SMEM_DYN);

    // routing
    k_zero<<<1, 32>>>();
    k_detect<<<64, 256>>>(cat);
    k_hist<<<64, 256>>>(cat);
    k_scan<<<1, 1>>>();
    k_perm<<<64, 256>>>(cat);

    // prep: features + weights -> transposed hi/lo bf16
    k_xprep<<<1024, 256>>>(feat, (__nv_bfloat16*)xh, (__nv_bfloat16*)xl, BROWS * C_IN / 4);
    k_wprep<<<256, 256>>>(We1, (__nv_bfloat16*)we1h, (__nv_bfloat16*)we1l, C_IN, H1, C_IN * H1);
    k_wprep<<<256, 256>>>(We2, (__nv_bfloat16*)we2h, (__nv_bfloat16*)we2l, H1, H2, H1 * H2);
    k_wprep<<<256, 256>>>(We3, (__nv_bfloat16*)we3h, (__nv_bfloat16*)we3l, H2, H3, H2 * H3);
    k_wprep<<<512, 256>>>(Wd1, (__nv_bfloat16*)wd1h, (__nv_bfloat16*)wd1l, H3, DECH, KCAT * H3 * DECH);
    k_wprep<<<512, 256>>>(Wd2, (__nv_bfloat16*)wd2h, (__nv_bfloat16*)wd2l, DECH, DECH, KCAT * DECH * DECH);
    k_wprep<<<512, 256>>>(Wd3, (__nv_bfloat16*)wd3h, (__nv_bfloat16*)wd3l, DECH, LATENT, KCAT * DECH * LATENT);

    // encoder
    k_mgemm<false, false, false, true, false><<<dim3(H1 / 128, BROWS / 128), 256, SMEM_DYN>>>(
        (__nv_bfloat16*)xh, (__nv_bfloat16*)xl, (__nv_bfloat16*)we1h, (__nv_bfloat16*)we1l, be1,
        nullptr, (__nv_bfloat16*)h1h, (__nv_bfloat16*)h1l, C_IN, H1, 0, 0);
    k_mgemm<false, false, false, true, false><<<dim3(H2 / 128, BROWS / 128), 256, SMEM_DYN>>>(
        (__nv_bfloat16*)h1h, (__nv_bfloat16*)h1l, (__nv_bfloat16*)we2h, (__nv_bfloat16*)we2l, be2,
        nullptr, (__nv_bfloat16*)h2h, (__nv_bfloat16*)h2l, H1, H2, 0, 0);
    k_mgemm<false, false, false, false, false><<<dim3(H3 / 128, BROWS / 128), 256, SMEM_DYN>>>(
        (__nv_bfloat16*)h2h, (__nv_bfloat16*)h2l, (__nv_bfloat16*)we3h, (__nv_bfloat16*)we3l, be3,
        nullptr, (__nv_bfloat16*)h3h, (__nv_bfloat16*)h3l, H2, H3, 0, 0);

    // routed decoders
    k_mgemm<true, true, false, true, false><<<dim3(DECH / 128, MAXT), 256, SMEM_DYN>>>(
        (__nv_bfloat16*)h3h, (__nv_bfloat16*)h3l, (__nv_bfloat16*)wd1h, (__nv_bfloat16*)wd1l, bd1,
        nullptr, (__nv_bfloat16*)d1h, (__nv_bfloat16*)d1l, H3, DECH, DECH * H3, DECH);
    k_mgemm<true, false, false, true, false><<<dim3(DECH / 128, MAXT), 256, SMEM_DYN>>>(
        (__nv_bfloat16*)d1h, (__nv_bfloat16*)d1l, (__nv_bfloat16*)wd2h, (__nv_bfloat16*)wd2l, bd2,
        nullptr, (__nv_bfloat16*)d2h, (__nv_bfloat16*)d2l, DECH, DECH, DECH * DECH, DECH);
    k_mgemm<true, false, true, false, true><<<dim3(LATENT / 128, MAXT), 256, SMEM_DYN>>>(
        (__nv_bfloat16*)d2h, (__nv_bfloat16*)d2l, (__nv_bfloat16*)wd3h, (__nv_bfloat16*)wd3l, bd3,
        out, nullptr, nullptr, DECH, LATENT, LATENT * DECH, LATENT);
}